// round 15
// baseline (speedup 1.0000x reference)
#include <cuda_runtime.h>
#include <math.h>
#include <stdint.h>

#define CONSUMERS 256
#define THREADS 288                               // 8 consumer warps + 1 producer warp
#define SLOTS 15
#define CELLS_PER_TILE 256
#define TILE_FLOATS (CELLS_PER_TILE * SLOTS)      // 3840 floats
#define TILE_BYTES  (TILE_FLOATS * 4)             // 15360 B
#define STAGES 3
#define PF_DIST 4                                 // L2 prefetch distance (tiles)
#define STAGE_FLOATS (2 * TILE_FLOATS)            // o tile + t tile
#define STAGE_BYTES  (2 * TILE_BYTES)             // 30720 B
#define SMEM_BYTES   (STAGES * STAGE_BYTES)       // 92160 B -> 2 CTAs/SM
#define GRID_CTAS 296
#define EPSF 1e-9f
#define LN2F 0.6931471805599453f

__device__ double g_loss_accum = 0.0;
__device__ unsigned int g_blocks_done = 0;

__device__ __forceinline__ uint32_t smem_u32(const void* p) {
    return (uint32_t)__cvta_generic_to_shared(p);
}
__device__ __forceinline__ void mbar_init(uint32_t mbar, uint32_t count) {
    asm volatile("mbarrier.init.shared.b64 [%0], %1;" :: "r"(mbar), "r"(count) : "memory");
}
__device__ __forceinline__ void mbar_expect_tx(uint32_t mbar, uint32_t bytes) {
    asm volatile("mbarrier.arrive.expect_tx.shared.b64 _, [%0], %1;" :: "r"(mbar), "r"(bytes) : "memory");
}
__device__ __forceinline__ void mbar_arrive(uint32_t mbar) {
    asm volatile("mbarrier.arrive.release.cta.shared.b64 _, [%0];" :: "r"(mbar) : "memory");
}
__device__ __forceinline__ void mbar_wait(uint32_t mbar, uint32_t parity) {
    uint32_t done;
    asm volatile(
        "{\n\t.reg .pred p;\n\t"
        "mbarrier.try_wait.parity.acquire.cta.shared::cta.b64 p, [%1], %2;\n\t"
        "selp.b32 %0, 1, 0, p;\n\t}"
        : "=r"(done) : "r"(mbar), "r"(parity) : "memory");
    if (!done) {
        asm volatile(
            "{\n\t.reg .pred P1;\n\t"
            "WAIT_LOOP_%=:\n\t"
            "mbarrier.try_wait.parity.acquire.cta.shared::cta.b64 P1, [%0], %1, 0x989680;\n\t"
            "@P1 bra.uni WAIT_DONE_%=;\n\t"
            "bra.uni WAIT_LOOP_%=;\n\t"
            "WAIT_DONE_%=:\n\t}"
            :: "r"(mbar), "r"(parity) : "memory");
    }
}
__device__ __forceinline__ void bulk_cp(uint32_t smem_dst, const void* gmem_src,
                                        uint32_t bytes, uint32_t mbar) {
    asm volatile(
        "cp.async.bulk.shared::cluster.global.mbarrier::complete_tx::bytes [%0], [%1], %2, [%3];"
        :: "r"(smem_dst), "l"(gmem_src), "r"(bytes), "r"(mbar) : "memory");
}
__device__ __forceinline__ void l2_prefetch(const void* gmem_src, uint32_t bytes) {
    asm volatile("cp.async.bulk.prefetch.L2.global [%0], %1;"
                 :: "l"(gmem_src), "r"(bytes) : "memory");
}
__device__ __forceinline__ float fast_sqrt(float x) {
    float r; asm("sqrt.approx.f32 %0, %1;" : "=f"(r) : "f"(x)); return r;
}
__device__ __forceinline__ float fast_lg2(float x) {
    float r; asm("lg2.approx.f32 %0, %1;" : "=f"(r) : "f"(x)); return r;
}

__global__ __launch_bounds__(THREADS)
void yolo_loss_pf_kernel(const float* __restrict__ o,
                         const float* __restrict__ t,
                         float* __restrict__ out,
                         int total_tiles, int nblocks) {
    extern __shared__ float smem[];                 // STAGES x [o tile | t tile]
    __shared__ uint64_t full_bar[STAGES];
    __shared__ uint64_t empty_bar[STAGES];
    __shared__ float warp_part[THREADS / 32];
    __shared__ bool is_last;

    const int tid = threadIdx.x;
    const int bid = blockIdx.x;

    // static contiguous partition (future tile indices known -> prefetchable)
    const int q = total_tiles / nblocks;
    const int rem = total_tiles - q * nblocks;
    const int my_n = q + (bid < rem ? 1 : 0);
    const int my_start = bid * q + (bid < rem ? bid : rem);

    if (tid == 0) {
        for (int s = 0; s < STAGES; s++) {
            mbar_init(smem_u32(&full_bar[s]), 1);               // producer arrive (+tx)
            mbar_init(smem_u32(&empty_bar[s]), CONSUMERS / 32); // elected arrive per warp
        }
        asm volatile("fence.proxy.async.shared::cta;" ::: "memory");
    }
    __syncthreads();

    float acc = 0.0f;

    if (tid == CONSUMERS) {
        // ---------------- producer: TMA fills + running L2 prefetch stream ----------------
        // Warm the L2 with the first PF_DIST tiles before the demand stream starts.
        for (int p = 0; p < PF_DIST && p < my_n; p++) {
            long long pb = (long long)(my_start + p) * TILE_FLOATS;
            l2_prefetch(o + pb, TILE_BYTES);
            l2_prefetch(t + pb, TILE_BYTES);
        }
        for (int j = 0; j < my_n; j++) {
            const int stage = j % STAGES;
            const uint32_t ep = 1u ^ (uint32_t)((j / STAGES) & 1); // first STAGES waits pass

            // prefetch tile j+PF_DIST before blocking on the empty barrier
            if (j + PF_DIST < my_n) {
                long long pb = (long long)(my_start + j + PF_DIST) * TILE_FLOATS;
                l2_prefetch(o + pb, TILE_BYTES);
                l2_prefetch(t + pb, TILE_BYTES);
            }

            mbar_wait(smem_u32(&empty_bar[stage]), ep);

            long long base = (long long)(my_start + j) * TILE_FLOATS;
            uint32_t so = smem_u32(smem + stage * STAGE_FLOATS);
            uint32_t mb = smem_u32(&full_bar[stage]);
            mbar_expect_tx(mb, STAGE_BYTES);
            bulk_cp(so, o + base, TILE_BYTES, mb);
            bulk_cp(so + TILE_BYTES, t + base, TILE_BYTES, mb);
        }
    } else if (tid < CONSUMERS) {
        // ---------------- consumers (256 threads, 8 warps) ----------------
        const int lid = tid & 31;
        for (int k = 0; k < my_n; k++) {
            const int stage = k % STAGES;
            const uint32_t fp = (uint32_t)((k / STAGES) & 1);
            mbar_wait(smem_u32(&full_bar[stage]), fp);

            const float* so = smem + stage * STAGE_FLOATS;
            const float* st = so + TILE_FLOATS;
            const float* co = so + tid * SLOTS;               // stride-15: conflict-free
            const float* ct = st + tid * SLOTS;

            const float o0 = co[0];
            float d0 = o0 - ct[0];
            float ow = co[2], tw = ct[2];
            float oh = co[3], th = ct[3];
            float loss = d0 * d0 + ow + tw + oh + th
                       - 2.0f * (fast_sqrt(ow * tw) + fast_sqrt(oh * th));

            float tc = ct[4];
            float oc = co[4];
            float l_pos = fast_lg2(oc + EPSF);
            float l_neg = fast_lg2(1.0f - oc + EPSF);
            loss -= LN2F * (tc * (l_pos - l_neg) + l_neg);

#pragma unroll
            for (int s = 5; s < 14; s++) {
                float d = ct[s] - co[s];
                loss = fmaf(d, d, loss);
            }
            acc += (o0 != 0.0f) ? loss : 0.0f;

            __syncwarp();                                     // warp done reading stage
            if (lid == 0)
                mbar_arrive(smem_u32(&empty_bar[stage]));
        }
    }

    // ---- block reduction ----
#pragma unroll
    for (int off = 16; off > 0; off >>= 1)
        acc += __shfl_xor_sync(0xFFFFFFFFu, acc, off);

    const int wid = tid >> 5;
    const int lid = tid & 31;
    if (lid == 0) warp_part[wid] = acc;
    __syncthreads();

    if (wid == 0) {
        float v = (lid < (THREADS / 32)) ? warp_part[lid] : 0.0f;
#pragma unroll
        for (int off = 16; off > 0; off >>= 1)
            v += __shfl_xor_sync(0xFFFFFFFFu, v, off);

        if (lid == 0) {
            atomicAdd(&g_loss_accum, (double)v);
            __threadfence();
            unsigned int done = atomicInc(&g_blocks_done, (unsigned int)(nblocks - 1));
            is_last = (done == (unsigned int)(nblocks - 1));
        }
    }
    __syncthreads();

    if (is_last && tid == 0) {
        __threadfence();
        out[0] = (float)g_loss_accum;
        g_loss_accum = 0.0;     // self-reset for graph replay determinism
    }
}

extern "C" void kernel_launch(void* const* d_in, const int* in_sizes, int n_in,
                              void* d_out, int out_size) {
    const float* o = (const float*)d_in[0];
    const float* t = (const float*)d_in[1];
    float* out = (float*)d_out;

    const long long total_floats = (long long)in_sizes[0];       // 512 * 47040
    const long long total_cells = total_floats / SLOTS;          // 1,605,632
    const int total_tiles = (int)(total_cells / CELLS_PER_TILE); // 6272 (exact)

    int nblocks = GRID_CTAS;
    if (nblocks > total_tiles) nblocks = total_tiles;

    cudaFuncSetAttribute(yolo_loss_pf_kernel,
                         cudaFuncAttributeMaxDynamicSharedMemorySize, SMEM_BYTES);

    yolo_loss_pf_kernel<<<nblocks, THREADS, SMEM_BYTES>>>(o, t, out, total_tiles, nblocks);
}

// round 16
// speedup vs baseline: 1.1947x; 1.1947x over previous
#include <cuda_runtime.h>
#include <math.h>
#include <stdint.h>

#define CONSUMERS 512
#define THREADS 544                               // 16 consumer warps + 1 producer warp
#define SLOTS 15
#define CELLS_PER_TILE 512
#define TILE_FLOATS (CELLS_PER_TILE * SLOTS)      // 7680 floats
#define TILE_BYTES  (TILE_FLOATS * 4)             // 30720 B
#define STAGES 3
#define STAGE_FLOATS (2 * TILE_FLOATS)            // o tile + t tile
#define STAGE_BYTES  (2 * TILE_BYTES)             // 61440 B
#define SMEM_BYTES   (STAGES * STAGE_BYTES)       // 184320 B -> 1 CTA/SM
#define GRID_CTAS 148
#define EPSF 1e-9f
#define LN2F 0.6931471805599453f

__device__ double g_loss_accum = 0.0;
__device__ unsigned int g_blocks_done = 0;
__device__ unsigned int g_tile_counter = 0;

__device__ __forceinline__ uint32_t smem_u32(const void* p) {
    return (uint32_t)__cvta_generic_to_shared(p);
}
__device__ __forceinline__ void mbar_init(uint32_t mbar, uint32_t count) {
    asm volatile("mbarrier.init.shared.b64 [%0], %1;" :: "r"(mbar), "r"(count) : "memory");
}
__device__ __forceinline__ void mbar_expect_tx(uint32_t mbar, uint32_t bytes) {
    asm volatile("mbarrier.arrive.expect_tx.shared.b64 _, [%0], %1;" :: "r"(mbar), "r"(bytes) : "memory");
}
__device__ __forceinline__ void mbar_arrive(uint32_t mbar) {
    asm volatile("mbarrier.arrive.release.cta.shared.b64 _, [%0];" :: "r"(mbar) : "memory");
}
__device__ __forceinline__ void mbar_wait(uint32_t mbar, uint32_t parity) {
    uint32_t done;
    asm volatile(
        "{\n\t.reg .pred p;\n\t"
        "mbarrier.try_wait.parity.acquire.cta.shared::cta.b64 p, [%1], %2;\n\t"
        "selp.b32 %0, 1, 0, p;\n\t}"
        : "=r"(done) : "r"(mbar), "r"(parity) : "memory");
    if (!done) {
        asm volatile(
            "{\n\t.reg .pred P1;\n\t"
            "WAIT_LOOP_%=:\n\t"
            "mbarrier.try_wait.parity.acquire.cta.shared::cta.b64 P1, [%0], %1, 0x989680;\n\t"
            "@P1 bra.uni WAIT_DONE_%=;\n\t"
            "bra.uni WAIT_LOOP_%=;\n\t"
            "WAIT_DONE_%=:\n\t}"
            :: "r"(mbar), "r"(parity) : "memory");
    }
}
__device__ __forceinline__ void bulk_cp(uint32_t smem_dst, const void* gmem_src,
                                        uint32_t bytes, uint32_t mbar) {
    asm volatile(
        "cp.async.bulk.shared::cluster.global.mbarrier::complete_tx::bytes [%0], [%1], %2, [%3];"
        :: "r"(smem_dst), "l"(gmem_src), "r"(bytes), "r"(mbar) : "memory");
}
__device__ __forceinline__ float fast_sqrt(float x) {
    float r; asm("sqrt.approx.f32 %0, %1;" : "=f"(r) : "f"(x)); return r;
}
__device__ __forceinline__ float fast_lg2(float x) {
    float r; asm("lg2.approx.f32 %0, %1;" : "=f"(r) : "f"(x)); return r;
}

__global__ __launch_bounds__(THREADS)
void yolo_loss_big_kernel(const float* __restrict__ o,
                          const float* __restrict__ t,
                          float* __restrict__ out,
                          int total_tiles, int nblocks) {
    extern __shared__ float smem[];                 // STAGES x [o tile | t tile]
    __shared__ uint64_t full_bar[STAGES];
    __shared__ uint64_t empty_bar[STAGES];
    __shared__ int stage_end[STAGES];
    __shared__ float warp_part[THREADS / 32];
    __shared__ bool is_last;

    const int tid = threadIdx.x;

    if (tid == 0) {
        for (int s = 0; s < STAGES; s++) {
            mbar_init(smem_u32(&full_bar[s]), 1);               // producer arrive (+tx)
            mbar_init(smem_u32(&empty_bar[s]), CONSUMERS / 32); // elected arrive per warp
            stage_end[s] = 0;
        }
        asm volatile("fence.proxy.async.shared::cta;" ::: "memory");
    }
    __syncthreads();

    float acc = 0.0f;

    if (tid == CONSUMERS) {
        // ------------- producer: atomic hoisted OUT of critical path -------------
        unsigned int tile = atomicAdd(&g_tile_counter, 1u);   // prefetch first index
        for (int j = 0; ; j++) {
            const int stage = j % STAGES;
            const uint32_t ep = 1u ^ (uint32_t)((j / STAGES) & 1); // first STAGES waits pass
            mbar_wait(smem_u32(&empty_bar[stage]), ep);       // ATOMG latency hidden here

            if (tile >= (unsigned int)total_tiles) {
                stage_end[stage] = 1;                         // sentinel: no data coming
                mbar_arrive(smem_u32(&full_bar[stage]));      // release orders flag store
                break;
            }
            long long base = (long long)tile * TILE_FLOATS;
            uint32_t so = smem_u32(smem + stage * STAGE_FLOATS);
            uint32_t mb = smem_u32(&full_bar[stage]);
            mbar_expect_tx(mb, STAGE_BYTES);
            bulk_cp(so, o + base, TILE_BYTES, mb);
            bulk_cp(so + TILE_BYTES, t + base, TILE_BYTES, mb);

            tile = atomicAdd(&g_tile_counter, 1u);            // prefetch next (off path)
        }
    } else if (tid < CONSUMERS) {
        // ---------------- consumers (512 threads, 16 warps) ----------------
        const int lid = tid & 31;
        for (int k = 0; ; k++) {
            const int stage = k % STAGES;
            const uint32_t fp = (uint32_t)((k / STAGES) & 1);
            mbar_wait(smem_u32(&full_bar[stage]), fp);
            if (stage_end[stage]) break;                      // sentinel -> done

            const float* so = smem + stage * STAGE_FLOATS;
            const float* st = so + TILE_FLOATS;
            const float* co = so + tid * SLOTS;               // stride-15: conflict-free
            const float* ct = st + tid * SLOTS;

            const float o0 = co[0];
            float d0 = o0 - ct[0];
            float ow = co[2], tw = ct[2];
            float oh = co[3], th = ct[3];
            float loss = d0 * d0 + ow + tw + oh + th
                       - 2.0f * (fast_sqrt(ow * tw) + fast_sqrt(oh * th));

            float tc = ct[4];
            float oc = co[4];
            float l_pos = fast_lg2(oc + EPSF);
            float l_neg = fast_lg2(1.0f - oc + EPSF);
            loss -= LN2F * (tc * (l_pos - l_neg) + l_neg);

#pragma unroll
            for (int s = 5; s < 14; s++) {
                float d = ct[s] - co[s];
                loss = fmaf(d, d, loss);
            }
            acc += (o0 != 0.0f) ? loss : 0.0f;

            __syncwarp();                                     // warp done reading stage
            if (lid == 0)
                mbar_arrive(smem_u32(&empty_bar[stage]));
        }
    }

    // ---- block reduction ----
#pragma unroll
    for (int off = 16; off > 0; off >>= 1)
        acc += __shfl_xor_sync(0xFFFFFFFFu, acc, off);

    const int wid = tid >> 5;
    const int lid = tid & 31;
    if (lid == 0) warp_part[wid] = acc;
    __syncthreads();

    if (wid == 0) {
        float v = (lid < (THREADS / 32)) ? warp_part[lid] : 0.0f;
#pragma unroll
        for (int off = 16; off > 0; off >>= 1)
            v += __shfl_xor_sync(0xFFFFFFFFu, v, off);

        if (lid == 0) {
            atomicAdd(&g_loss_accum, (double)v);
            __threadfence();
            unsigned int done = atomicInc(&g_blocks_done, (unsigned int)(nblocks - 1));
            is_last = (done == (unsigned int)(nblocks - 1));
        }
    }
    __syncthreads();

    if (is_last && tid == 0) {
        __threadfence();
        out[0] = (float)g_loss_accum;
        g_loss_accum = 0.0;     // self-reset for graph replay determinism
        g_tile_counter = 0;
    }
}

extern "C" void kernel_launch(void* const* d_in, const int* in_sizes, int n_in,
                              void* d_out, int out_size) {
    const float* o = (const float*)d_in[0];
    const float* t = (const float*)d_in[1];
    float* out = (float*)d_out;

    const long long total_floats = (long long)in_sizes[0];       // 512 * 47040
    const long long total_cells = total_floats / SLOTS;          // 1,605,632
    const int total_tiles = (int)(total_cells / CELLS_PER_TILE); // 3136 (exact)

    int nblocks = GRID_CTAS;
    if (nblocks > total_tiles) nblocks = total_tiles;

    cudaFuncSetAttribute(yolo_loss_big_kernel,
                         cudaFuncAttributeMaxDynamicSharedMemorySize, SMEM_BYTES);

    yolo_loss_big_kernel<<<nblocks, THREADS, SMEM_BYTES>>>(o, t, out, total_tiles, nblocks);
}

// round 17
// speedup vs baseline: 1.2510x; 1.0471x over previous
#include <cuda_runtime.h>
#include <math.h>
#include <stdint.h>

#define CONSUMERS 256
#define THREADS 288                               // 8 consumer warps + 1 producer warp
#define SLOTS 15
#define CELLS_PER_TILE 256
#define TILE_FLOATS (CELLS_PER_TILE * SLOTS)      // 3840 floats
#define TILE_BYTES  (TILE_FLOATS * 4)             // 15360 B
#define STAGES 6                                  // deep pipeline: 6 slots, 1 producer
#define STAGE_FLOATS (2 * TILE_FLOATS)            // o tile + t tile
#define STAGE_BYTES  (2 * TILE_BYTES)             // 30720 B
#define SMEM_BYTES   (STAGES * STAGE_BYTES)       // 184320 B -> 1 CTA/SM
#define GRID_CTAS 148
#define EPSF 1e-9f
#define LN2F 0.6931471805599453f

__device__ double g_loss_accum = 0.0;
__device__ unsigned int g_blocks_done = 0;
__device__ unsigned int g_tile_counter = 0;

__device__ __forceinline__ uint32_t smem_u32(const void* p) {
    return (uint32_t)__cvta_generic_to_shared(p);
}
__device__ __forceinline__ void mbar_init(uint32_t mbar, uint32_t count) {
    asm volatile("mbarrier.init.shared.b64 [%0], %1;" :: "r"(mbar), "r"(count) : "memory");
}
__device__ __forceinline__ void mbar_expect_tx(uint32_t mbar, uint32_t bytes) {
    asm volatile("mbarrier.arrive.expect_tx.shared.b64 _, [%0], %1;" :: "r"(mbar), "r"(bytes) : "memory");
}
__device__ __forceinline__ void mbar_arrive(uint32_t mbar) {
    asm volatile("mbarrier.arrive.release.cta.shared.b64 _, [%0];" :: "r"(mbar) : "memory");
}
__device__ __forceinline__ void mbar_wait(uint32_t mbar, uint32_t parity) {
    uint32_t done;
    asm volatile(
        "{\n\t.reg .pred p;\n\t"
        "mbarrier.try_wait.parity.acquire.cta.shared::cta.b64 p, [%1], %2;\n\t"
        "selp.b32 %0, 1, 0, p;\n\t}"
        : "=r"(done) : "r"(mbar), "r"(parity) : "memory");
    if (!done) {
        asm volatile(
            "{\n\t.reg .pred P1;\n\t"
            "WAIT_LOOP_%=:\n\t"
            "mbarrier.try_wait.parity.acquire.cta.shared::cta.b64 P1, [%0], %1, 0x989680;\n\t"
            "@P1 bra.uni WAIT_DONE_%=;\n\t"
            "bra.uni WAIT_LOOP_%=;\n\t"
            "WAIT_DONE_%=:\n\t}"
            :: "r"(mbar), "r"(parity) : "memory");
    }
}
__device__ __forceinline__ void bulk_cp(uint32_t smem_dst, const void* gmem_src,
                                        uint32_t bytes, uint32_t mbar) {
    asm volatile(
        "cp.async.bulk.shared::cluster.global.mbarrier::complete_tx::bytes [%0], [%1], %2, [%3];"
        :: "r"(smem_dst), "l"(gmem_src), "r"(bytes), "r"(mbar) : "memory");
}
__device__ __forceinline__ float fast_sqrt(float x) {
    float r; asm("sqrt.approx.f32 %0, %1;" : "=f"(r) : "f"(x)); return r;
}
__device__ __forceinline__ float fast_lg2(float x) {
    float r; asm("lg2.approx.f32 %0, %1;" : "=f"(r) : "f"(x)); return r;
}

__global__ __launch_bounds__(THREADS)
void yolo_loss_deep_kernel(const float* __restrict__ o,
                           const float* __restrict__ t,
                           float* __restrict__ out,
                           int total_tiles, int nblocks) {
    extern __shared__ float smem[];                 // STAGES x [o tile | t tile]
    __shared__ uint64_t full_bar[STAGES];
    __shared__ uint64_t empty_bar[STAGES];
    __shared__ int stage_end[STAGES];
    __shared__ float warp_part[THREADS / 32];
    __shared__ bool is_last;

    const int tid = threadIdx.x;

    if (tid == 0) {
        for (int s = 0; s < STAGES; s++) {
            mbar_init(smem_u32(&full_bar[s]), 1);               // producer arrive (+tx)
            mbar_init(smem_u32(&empty_bar[s]), CONSUMERS / 32); // elected arrive per warp
            stage_end[s] = 0;
        }
        asm volatile("fence.proxy.async.shared::cta;" ::: "memory");
    }
    __syncthreads();

    float acc = 0.0f;

    if (tid == CONSUMERS) {
        // ------------- producer: atomic hoisted OUT of critical path -------------
        unsigned int tile = atomicAdd(&g_tile_counter, 1u);   // prefetch first index
        for (int j = 0; ; j++) {
            const int stage = j % STAGES;
            const uint32_t ep = 1u ^ (uint32_t)((j / STAGES) & 1); // first STAGES waits pass
            mbar_wait(smem_u32(&empty_bar[stage]), ep);       // ATOMG latency hidden here

            if (tile >= (unsigned int)total_tiles) {
                stage_end[stage] = 1;                         // sentinel: no data coming
                mbar_arrive(smem_u32(&full_bar[stage]));      // release orders flag store
                break;
            }
            long long base = (long long)tile * TILE_FLOATS;
            uint32_t so = smem_u32(smem + stage * STAGE_FLOATS);
            uint32_t mb = smem_u32(&full_bar[stage]);
            mbar_expect_tx(mb, STAGE_BYTES);
            bulk_cp(so, o + base, TILE_BYTES, mb);
            bulk_cp(so + TILE_BYTES, t + base, TILE_BYTES, mb);

            tile = atomicAdd(&g_tile_counter, 1u);            // prefetch next (off path)
        }
    } else if (tid < CONSUMERS) {
        // ---------------- consumers (256 threads, 8 warps) ----------------
        const int lid = tid & 31;
        for (int k = 0; ; k++) {
            const int stage = k % STAGES;
            const uint32_t fp = (uint32_t)((k / STAGES) & 1);
            mbar_wait(smem_u32(&full_bar[stage]), fp);
            if (stage_end[stage]) break;                      // sentinel -> done

            const float* so = smem + stage * STAGE_FLOATS;
            const float* st = so + TILE_FLOATS;
            const float* co = so + tid * SLOTS;               // stride-15: conflict-free
            const float* ct = st + tid * SLOTS;

            const float o0 = co[0];
            float d0 = o0 - ct[0];
            float ow = co[2], tw = ct[2];
            float oh = co[3], th = ct[3];
            float loss = d0 * d0 + ow + tw + oh + th
                       - 2.0f * (fast_sqrt(ow * tw) + fast_sqrt(oh * th));

            float tc = ct[4];
            float oc = co[4];
            float l_pos = fast_lg2(oc + EPSF);
            float l_neg = fast_lg2(1.0f - oc + EPSF);
            loss -= LN2F * (tc * (l_pos - l_neg) + l_neg);

#pragma unroll
            for (int s = 5; s < 14; s++) {
                float d = ct[s] - co[s];
                loss = fmaf(d, d, loss);
            }
            acc += (o0 != 0.0f) ? loss : 0.0f;

            __syncwarp();                                     // warp done reading stage
            if (lid == 0)
                mbar_arrive(smem_u32(&empty_bar[stage]));
        }
    }

    // ---- block reduction ----
#pragma unroll
    for (int off = 16; off > 0; off >>= 1)
        acc += __shfl_xor_sync(0xFFFFFFFFu, acc, off);

    const int wid = tid >> 5;
    const int lid = tid & 31;
    if (lid == 0) warp_part[wid] = acc;
    __syncthreads();

    if (wid == 0) {
        float v = (lid < (THREADS / 32)) ? warp_part[lid] : 0.0f;
#pragma unroll
        for (int off = 16; off > 0; off >>= 1)
            v += __shfl_xor_sync(0xFFFFFFFFu, v, off);

        if (lid == 0) {
            atomicAdd(&g_loss_accum, (double)v);
            __threadfence();
            unsigned int done = atomicInc(&g_blocks_done, (unsigned int)(nblocks - 1));
            is_last = (done == (unsigned int)(nblocks - 1));
        }
    }
    __syncthreads();

    if (is_last && tid == 0) {
        __threadfence();
        out[0] = (float)g_loss_accum;
        g_loss_accum = 0.0;     // self-reset for graph replay determinism
        g_tile_counter = 0;
    }
}

extern "C" void kernel_launch(void* const* d_in, const int* in_sizes, int n_in,
                              void* d_out, int out_size) {
    const float* o = (const float*)d_in[0];
    const float* t = (const float*)d_in[1];
    float* out = (float*)d_out;

    const long long total_floats = (long long)in_sizes[0];       // 512 * 47040
    const long long total_cells = total_floats / SLOTS;          // 1,605,632
    const int total_tiles = (int)(total_cells / CELLS_PER_TILE); // 6272 (exact)

    int nblocks = GRID_CTAS;
    if (nblocks > total_tiles) nblocks = total_tiles;

    cudaFuncSetAttribute(yolo_loss_deep_kernel,
                         cudaFuncAttributeMaxDynamicSharedMemorySize, SMEM_BYTES);

    yolo_loss_deep_kernel<<<nblocks, THREADS, SMEM_BYTES>>>(o, t, out, total_tiles, nblocks);
}